// round 8
// baseline (speedup 1.0000x reference)
#include <cuda_runtime.h>
#include <cuda_bf16.h>

#define N_NODES  100000
#define N_EDGES  3200000
#define E_TOT    (N_EDGES + N_NODES)   // edges + self loops
#define IN_DIM   128
#define H1F1     64                    // 8 heads x 8 feats
#define NCLS     40
#define NEG_SLOPE 0.2f
#define SCAN_TB  256
#define SCAN_NB  ((N_NODES + SCAN_TB - 1) / SCAN_TB)   // 391

// ---------------- scratch (static device globals; 16B-aligned) -------------
static __device__ __align__(16) int   g_deg [N_NODES];
static __device__ __align__(16) int   g_off [N_NODES + 1];
static __device__ __align__(16) int   g_cur [N_NODES];
static __device__ __align__(16) int   g_bsum [SCAN_NB];
static __device__ __align__(16) int   g_bbase[SCAN_NB];
static __device__ __align__(16) int   g_eidx[E_TOT];          // src per CSR slot
static __device__ __align__(16) float g_h1 [N_NODES * H1F1];
static __device__ __align__(16) float g_es1[N_NODES * 8];
static __device__ __align__(16) float g_ed1[N_NODES * 8];
static __device__ __align__(16) float g_out1[N_NODES * H1F1]; // normalized layer-1 output
static __device__ __align__(16) float g_h2 [N_NODES * NCLS];
static __device__ __align__(16) float g_es2[N_NODES];
static __device__ __align__(16) float g_ed2[N_NODES];
static __device__ int g_is64;

// exp(leaky_relu(a+b))
__device__ __forceinline__ float pexp(float a, float b) {
    float e = a + b;
    e = (e > 0.f) ? e : NEG_SLOPE * e;
    return __expf(e);
}

// ---------------- K_detect: adjacency int64 or int32? ----------------------
__global__ void k_detect(const long long* __restrict__ adj64) {
    if (blockIdx.x == 0 && threadIdx.x == 0) {
        int ok = 1;
        for (int i = 0; i < 64; i++) {
            long long v = adj64[i];
            if (v < 0 || v >= N_NODES) ok = 0;
        }
        g_is64 = ok;
    }
}

// ---------------- deg init: 1 (self loop) -----------------------------------
__global__ void k_init_deg() {
    int i = blockIdx.x * blockDim.x + threadIdx.x;
    if (i < N_NODES) g_deg[i] = 1;
}

// ---------------- degree histogram (reads dst half of adj only) -------------
__global__ void k_deg(const void* __restrict__ adjv) {
    int i = blockIdx.x * blockDim.x + threadIdx.x;
    if (i >= N_EDGES) return;
    int d;
    if (g_is64) d = (int)((const long long*)adjv)[i + N_EDGES];
    else        d = ((const int*)adjv)[i + N_EDGES];
    d = min(max(d, 0), N_NODES - 1);
    atomicAdd(&g_deg[d], 1);
}

// ---------------- 3-phase grid scan -----------------------------------------
__global__ __launch_bounds__(SCAN_TB)
void k_scan_local() {
    __shared__ int sh[SCAN_TB];
    int b = blockIdx.x, t = threadIdx.x;
    int i = b * SCAN_TB + t;
    int v = (i < N_NODES) ? g_deg[i] : 0;
    sh[t] = v;
    __syncthreads();
#pragma unroll
    for (int off = 1; off < SCAN_TB; off <<= 1) {
        int u = (t >= off) ? sh[t - off] : 0;
        __syncthreads();
        sh[t] += u;
        __syncthreads();
    }
    if (i < N_NODES) g_off[i] = sh[t] - v;
    if (t == SCAN_TB - 1) g_bsum[b] = sh[t];
}

__global__ __launch_bounds__(512)
void k_scan_base() {
    __shared__ int sh[512];
    int t = threadIdx.x;
    int v = (t < SCAN_NB) ? g_bsum[t] : 0;
    sh[t] = v;
    __syncthreads();
#pragma unroll
    for (int off = 1; off < 512; off <<= 1) {
        int u = (t >= off) ? sh[t - off] : 0;
        __syncthreads();
        sh[t] += u;
        __syncthreads();
    }
    if (t < SCAN_NB) g_bbase[t] = sh[t] - v;
}

__global__ __launch_bounds__(SCAN_TB)
void k_scan_final() {
    int b = blockIdx.x, t = threadIdx.x;
    int i = b * SCAN_TB + t;
    if (i < N_NODES) {
        int o = g_off[i] + g_bbase[b];
        g_off[i] = o;
        g_cur[i] = o;
    }
    if (i == 0) g_off[N_NODES] = E_TOT;
}

// ---------------- scatter: fill CSR src lists straight from adj -------------
__global__ void k_scatter(const void* __restrict__ adjv) {
    int e = blockIdx.x * blockDim.x + threadIdx.x;
    if (e >= E_TOT) return;
    int s, d;
    if (e < N_EDGES) {
        if (g_is64) {
            const long long* a = (const long long*)adjv;
            s = (int)a[e]; d = (int)a[e + N_EDGES];
        } else {
            const int* a = (const int*)adjv;
            s = a[e]; d = a[e + N_EDGES];
        }
        s = min(max(s, 0), N_NODES - 1);
        d = min(max(d, 0), N_NODES - 1);
    } else {
        s = d = e - N_EDGES;
    }
    int pos = atomicAdd(&g_cur[d], 1);
    g_eidx[pos] = s;
}

// ---------------- K1: h1 = x @ W1 ; es1/ed1  (4 nodes x 16 feats / thread) --
__global__ __launch_bounds__(128)
void k_gemm1(const float* __restrict__ x, const float* __restrict__ W1,
             const float* __restrict__ a1s, const float* __restrict__ a1d) {
    __shared__ float Wsm[IN_DIM * H1F1];      // 32 KB, [k][64]
    __shared__ float Asm[64], Bsm[64];
    int tid = threadIdx.x;
    {
        const float4* w4 = (const float4*)W1;
        float4* s4 = (float4*)Wsm;
#pragma unroll
        for (int t = tid; t < IN_DIM * H1F1 / 4; t += 128) s4[t] = w4[t];
        if (tid < 64) { Asm[tid] = a1s[tid]; Bsm[tid] = a1d[tid]; }
    }
    __syncthreads();

    int fs   = tid >> 5;          // feature slice 0..3 -> feats [fs*16, fs*16+16)
    int lane = tid & 31;
    int base = blockIdx.x * 128;  // block covers 128 nodes

    int  n[4]; bool val[4];
    const float4* xr[4];
#pragma unroll
    for (int i = 0; i < 4; i++) {
        n[i]   = base + i * 32 + lane;
        val[i] = n[i] < N_NODES;
        int nr = val[i] ? n[i] : N_NODES - 1;
        xr[i]  = (const float4*)(x + (size_t)nr * IN_DIM);
    }

    float acc[4][16];
#pragma unroll
    for (int i = 0; i < 4; i++)
#pragma unroll
        for (int j = 0; j < 16; j++) acc[i][j] = 0.f;

#pragma unroll 2
    for (int kk = 0; kk < IN_DIM / 4; kk++) {
        float xs[4][4];
#pragma unroll
        for (int i = 0; i < 4; i++) {
            float4 xv = __ldg(xr[i] + kk);
            xs[i][0] = xv.x; xs[i][1] = xv.y; xs[i][2] = xv.z; xs[i][3] = xv.w;
        }
#pragma unroll
        for (int u = 0; u < 4; u++) {
            const float4* wr = (const float4*)&Wsm[(kk * 4 + u) * H1F1 + fs * 16];
            float4 w0 = wr[0], w1 = wr[1], w2 = wr[2], w3 = wr[3];
#pragma unroll
            for (int i = 0; i < 4; i++) {
                float xv = xs[i][u];
                acc[i][ 0] += xv * w0.x; acc[i][ 1] += xv * w0.y;
                acc[i][ 2] += xv * w0.z; acc[i][ 3] += xv * w0.w;
                acc[i][ 4] += xv * w1.x; acc[i][ 5] += xv * w1.y;
                acc[i][ 6] += xv * w1.z; acc[i][ 7] += xv * w1.w;
                acc[i][ 8] += xv * w2.x; acc[i][ 9] += xv * w2.y;
                acc[i][10] += xv * w2.z; acc[i][11] += xv * w2.w;
                acc[i][12] += xv * w3.x; acc[i][13] += xv * w3.y;
                acc[i][14] += xv * w3.z; acc[i][15] += xv * w3.w;
            }
        }
    }

    int h0 = fs * 2, h1 = fs * 2 + 1;   // the two heads this thread owns
#pragma unroll
    for (int i = 0; i < 4; i++) {
        if (!val[i]) continue;
        float4* ho = (float4*)&g_h1[(size_t)n[i] * H1F1 + fs * 16];
#pragma unroll
        for (int j4 = 0; j4 < 4; j4++)
            ho[j4] = make_float4(acc[i][j4*4+0], acc[i][j4*4+1],
                                 acc[i][j4*4+2], acc[i][j4*4+3]);
        float es0 = 0.f, ed0 = 0.f, es1 = 0.f, ed1 = 0.f;
#pragma unroll
        for (int f = 0; f < 8; f++) {
            es0 += acc[i][f]     * Asm[h0 * 8 + f];
            ed0 += acc[i][f]     * Bsm[h0 * 8 + f];
            es1 += acc[i][8 + f] * Asm[h1 * 8 + f];
            ed1 += acc[i][8 + f] * Bsm[h1 * 8 + f];
        }
        g_es1[n[i] * 8 + h0] = es0;  g_ed1[n[i] * 8 + h0] = ed0;
        g_es1[n[i] * 8 + h1] = es1;  g_ed1[n[i] * 8 + h1] = ed1;
    }
}

// ---------------- K2: layer1 CSR aggregate (1 warp per dst node) ------------
// coalesced 32-edge index load + shfl broadcast
__global__ __launch_bounds__(256)
void k_l1_csr() {
    int w    = (blockIdx.x * blockDim.x + threadIdx.x) >> 5;
    int lane = threadIdx.x & 31;
    if (w >= N_NODES) return;
    int d = w;
    float ed = __ldg(&g_ed1[d * 8 + (lane >> 2)]);   // lane's head = lane/4
    int beg = g_off[d], end = g_off[d + 1];
    float a0 = 0.f, a1 = 0.f, sw = 0.f;
    for (int jb = beg; jb < end; jb += 32) {
        int rem  = end - jb;
        int myid = (lane < rem) ? g_eidx[jb + lane] : 0;
        int cnt  = min(32, rem);
        for (int t = 0; t < cnt; t++) {
            int s = __shfl_sync(0xffffffffu, myid, t);
            float es = __ldg(&g_es1[s * 8 + (lane >> 2)]);
            float wgt = pexp(es, ed);
            float2 h = *(const float2*)&g_h1[(size_t)s * H1F1 + lane * 2];
            a0 += wgt * h.x;
            a1 += wgt * h.y;
            sw += wgt;
        }
    }
    float inv = 1.f / sw;
    *(float2*)&g_out1[(size_t)d * H1F1 + lane * 2] = make_float2(a0 * inv, a1 * inv);
}

// ---------------- K3: x2 = elu(out1) ; h2 = x2 @ W2 ; es2/ed2 ---------------
__global__ __launch_bounds__(256)
void k_gemm2(const float* __restrict__ W2,
             const float* __restrict__ a2s, const float* __restrict__ a2d) {
    __shared__ float Wsm[H1F1 * NCLS];   // 10 KB
    __shared__ float Asm[NCLS], Bsm[NCLS];
    int tid = threadIdx.x;
    for (int t = tid; t < H1F1 * NCLS; t += 256) Wsm[t] = W2[t];
    if (tid < NCLS) { Asm[tid] = a2s[tid]; Bsm[tid] = a2d[tid]; }
    __syncthreads();

    int node = blockIdx.x * 256 + tid;
    if (node >= N_NODES) return;

    float acc[NCLS];
#pragma unroll
    for (int c = 0; c < NCLS; c++) acc[c] = 0.f;

    const float4* xrow = (const float4*)&g_out1[(size_t)node * H1F1];
#pragma unroll 4
    for (int kk = 0; kk < H1F1 / 4; kk++) {
        float4 xv = xrow[kk];
        float xs4[4];
        xs4[0] = xv.x > 0.f ? xv.x : expm1f(xv.x);
        xs4[1] = xv.y > 0.f ? xv.y : expm1f(xv.y);
        xs4[2] = xv.z > 0.f ? xv.z : expm1f(xv.z);
        xs4[3] = xv.w > 0.f ? xv.w : expm1f(xv.w);
#pragma unroll
        for (int u = 0; u < 4; u++) {
            float xs = xs4[u];
            const float4* wr = (const float4*)&Wsm[(kk * 4 + u) * NCLS];
#pragma unroll
            for (int c4 = 0; c4 < NCLS / 4; c4++) {
                float4 w = wr[c4];
                acc[c4 * 4 + 0] += xs * w.x;
                acc[c4 * 4 + 1] += xs * w.y;
                acc[c4 * 4 + 2] += xs * w.z;
                acc[c4 * 4 + 3] += xs * w.w;
            }
        }
    }
    float4* hout = (float4*)&g_h2[(size_t)node * NCLS];
#pragma unroll
    for (int c4 = 0; c4 < NCLS / 4; c4++)
        hout[c4] = make_float4(acc[c4*4+0], acc[c4*4+1], acc[c4*4+2], acc[c4*4+3]);

    float es = 0.f, ed = 0.f;
#pragma unroll
    for (int c = 0; c < NCLS; c++) { es += acc[c] * Asm[c]; ed += acc[c] * Bsm[c]; }
    g_es2[node] = es;
    g_ed2[node] = ed;
}

// ---------------- K4: layer2 CSR aggregate + fused log_softmax --------------
__global__ __launch_bounds__(256)
void k_l2_csr(float* __restrict__ out) {
    int w    = (blockIdx.x * blockDim.x + threadIdx.x) >> 5;
    int lane = threadIdx.x & 31;
    if (w >= N_NODES) return;
    int d = w;
    float ed = __ldg(&g_ed2[d]);
    int beg = g_off[d], end = g_off[d + 1];
    float a0 = 0.f, a1 = 0.f, sw = 0.f;
    bool act = lane < NCLS / 2;
    for (int jb = beg; jb < end; jb += 32) {
        int rem  = end - jb;
        int myid = (lane < rem) ? g_eidx[jb + lane] : 0;
        int cnt  = min(32, rem);
        for (int t = 0; t < cnt; t++) {
            int s = __shfl_sync(0xffffffffu, myid, t);
            float es = __ldg(&g_es2[s]);
            float wgt = pexp(es, ed);
            if (act) {
                float2 h = *(const float2*)&g_h2[(size_t)s * NCLS + lane * 2];
                a0 += wgt * h.x;
                a1 += wgt * h.y;
            }
            sw += wgt;
        }
    }
    float inv = 1.f / sw;
    float v0 = a0 * inv, v1 = a1 * inv;
    float m = act ? fmaxf(v0, v1) : -1e30f;
#pragma unroll
    for (int o = 16; o; o >>= 1) m = fmaxf(m, __shfl_xor_sync(0xffffffffu, m, o));
    float ssum = act ? (expf(v0 - m) + expf(v1 - m)) : 0.f;
#pragma unroll
    for (int o = 16; o; o >>= 1) ssum += __shfl_xor_sync(0xffffffffu, ssum, o);
    float lse = m + logf(ssum);
    if (act)
        *(float2*)&out[(size_t)d * NCLS + lane * 2] = make_float2(v0 - lse, v1 - lse);
}

// ---------------- launch ----------------------------------------------------
extern "C" void kernel_launch(void* const* d_in, const int* in_sizes, int n_in,
                              void* d_out, int out_size) {
    int ix = -1, ia = -1, iw1 = -1, iw2 = -1;
    int p64[2] = {-1, -1}, p40[2] = {-1, -1};
    for (int i = 0; i < n_in; i++) {
        switch (in_sizes[i]) {
            case N_NODES * IN_DIM:   ix  = i; break;
            case 2 * N_EDGES:        ia  = i; break;
            case IN_DIM * H1F1:      iw1 = i; break;
            case H1F1 * NCLS:        iw2 = i; break;
            case 64: (p64[0] < 0 ? p64[0] : p64[1]) = i; break;
            case 40: (p40[0] < 0 ? p40[0] : p40[1]) = i; break;
        }
    }
    bool alpha = (n_in > 0 && in_sizes[0] == IN_DIM * H1F1);
    int ia1s = alpha ? p64[1] : p64[0], ia1d = alpha ? p64[0] : p64[1];
    int ia2s = alpha ? p40[1] : p40[0], ia2d = alpha ? p40[0] : p40[1];

    const float* x   = (const float*)d_in[ix];
    const void*  adj = d_in[ia];
    const float* W1  = (const float*)d_in[iw1];
    const float* a1s = (const float*)d_in[ia1s];
    const float* a1d = (const float*)d_in[ia1d];
    const float* W2  = (const float*)d_in[iw2];
    const float* a2s = (const float*)d_in[ia2s];
    const float* a2d = (const float*)d_in[ia2d];
    float* out = (float*)d_out;

    const int TB = 256;
    int warpBlocks = (N_NODES * 32 + TB - 1) / TB;   // 1 warp per node

    k_detect<<<1, 32>>>((const long long*)adj);
    k_init_deg<<<(N_NODES + TB - 1) / TB, TB>>>();
    k_deg<<<(N_EDGES + TB - 1) / TB, TB>>>(adj);
    k_scan_local<<<SCAN_NB, SCAN_TB>>>();
    k_scan_base<<<1, 512>>>();
    k_scan_final<<<SCAN_NB, SCAN_TB>>>();
    k_scatter<<<(E_TOT + TB - 1) / TB, TB>>>(adj);
    k_gemm1<<<(N_NODES + 127) / 128, 128>>>(x, W1, a1s, a1d);
    k_l1_csr<<<warpBlocks, TB>>>();
    k_gemm2<<<(N_NODES + TB - 1) / TB, TB>>>(W2, a2s, a2d);
    k_l2_csr<<<warpBlocks, TB>>>(out);
}

// round 11
// speedup vs baseline: 1.0488x; 1.0488x over previous
#include <cuda_runtime.h>
#include <cuda_bf16.h>

#define N_NODES  100000
#define N_EDGES  3200000
#define E_TOT    (N_EDGES + N_NODES)   // edges + self loops
#define IN_DIM   128
#define H1F1     64                    // 8 heads x 8 feats
#define NCLS     40
#define NEG_SLOPE 0.2f
#define SCAN_TB  256
#define SCAN_NB  ((N_NODES + SCAN_TB - 1) / SCAN_TB)   // 391

// ---------------- scratch (static device globals; 16B-aligned) -------------
static __device__ __align__(16) int   g_deg [N_NODES];
static __device__ __align__(16) int   g_off [N_NODES + 1];
static __device__ __align__(16) int   g_cur [N_NODES];
static __device__ __align__(16) int   g_bsum [SCAN_NB];
static __device__ __align__(16) int   g_bbase[SCAN_NB];
static __device__ __align__(16) int   g_eidx[E_TOT];          // src per CSR slot
static __device__ __align__(16) float g_h1 [N_NODES * H1F1];
static __device__ __align__(16) float g_es1[N_NODES * 8];
static __device__ __align__(16) float g_ed1[N_NODES * 8];
static __device__ __align__(16) float g_out1[N_NODES * H1F1]; // normalized layer-1 output
static __device__ __align__(16) float g_h2 [N_NODES * NCLS];
static __device__ __align__(16) float g_es2[N_NODES];
static __device__ __align__(16) float g_ed2[N_NODES];
static __device__ int g_is64;

// exp(leaky_relu(a+b))
__device__ __forceinline__ float pexp(float a, float b) {
    float e = a + b;
    e = (e > 0.f) ? e : NEG_SLOPE * e;
    return __expf(e);
}

// ---------------- K_detect: adjacency int64 or int32? ----------------------
__global__ void k_detect(const long long* __restrict__ adj64) {
    if (blockIdx.x == 0 && threadIdx.x == 0) {
        int ok = 1;
        for (int i = 0; i < 64; i++) {
            long long v = adj64[i];
            if (v < 0 || v >= N_NODES) ok = 0;
        }
        g_is64 = ok;
    }
}

// ---------------- deg init: 1 (self loop) -----------------------------------
__global__ void k_init_deg() {
    int i = blockIdx.x * blockDim.x + threadIdx.x;
    if (i < N_NODES) g_deg[i] = 1;
}

// ---------------- degree histogram (reads dst half of adj only) -------------
__global__ void k_deg(const void* __restrict__ adjv) {
    int i = blockIdx.x * blockDim.x + threadIdx.x;
    if (i >= N_EDGES) return;
    int d;
    if (g_is64) d = (int)((const long long*)adjv)[i + N_EDGES];
    else        d = ((const int*)adjv)[i + N_EDGES];
    d = min(max(d, 0), N_NODES - 1);
    atomicAdd(&g_deg[d], 1);
}

// ---------------- 3-phase grid scan -----------------------------------------
__global__ __launch_bounds__(SCAN_TB)
void k_scan_local() {
    __shared__ int sh[SCAN_TB];
    int b = blockIdx.x, t = threadIdx.x;
    int i = b * SCAN_TB + t;
    int v = (i < N_NODES) ? g_deg[i] : 0;
    sh[t] = v;
    __syncthreads();
#pragma unroll
    for (int off = 1; off < SCAN_TB; off <<= 1) {
        int u = (t >= off) ? sh[t - off] : 0;
        __syncthreads();
        sh[t] += u;
        __syncthreads();
    }
    if (i < N_NODES) g_off[i] = sh[t] - v;
    if (t == SCAN_TB - 1) g_bsum[b] = sh[t];
}

__global__ __launch_bounds__(512)
void k_scan_base() {
    __shared__ int sh[512];
    int t = threadIdx.x;
    int v = (t < SCAN_NB) ? g_bsum[t] : 0;
    sh[t] = v;
    __syncthreads();
#pragma unroll
    for (int off = 1; off < 512; off <<= 1) {
        int u = (t >= off) ? sh[t - off] : 0;
        __syncthreads();
        sh[t] += u;
        __syncthreads();
    }
    if (t < SCAN_NB) g_bbase[t] = sh[t] - v;
}

__global__ __launch_bounds__(SCAN_TB)
void k_scan_final() {
    int b = blockIdx.x, t = threadIdx.x;
    int i = b * SCAN_TB + t;
    if (i < N_NODES) {
        int o = g_off[i] + g_bbase[b];
        g_off[i] = o;
        g_cur[i] = o;
    }
    if (i == 0) g_off[N_NODES] = E_TOT;
}

// ---------------- scatter: fill CSR src lists straight from adj -------------
__global__ void k_scatter(const void* __restrict__ adjv) {
    int e = blockIdx.x * blockDim.x + threadIdx.x;
    if (e >= E_TOT) return;
    int s, d;
    if (e < N_EDGES) {
        if (g_is64) {
            const long long* a = (const long long*)adjv;
            s = (int)a[e]; d = (int)a[e + N_EDGES];
        } else {
            const int* a = (const int*)adjv;
            s = a[e]; d = a[e + N_EDGES];
        }
        s = min(max(s, 0), N_NODES - 1);
        d = min(max(d, 0), N_NODES - 1);
    } else {
        s = d = e - N_EDGES;
    }
    int pos = atomicAdd(&g_cur[d], 1);
    g_eidx[pos] = s;
}

// ---------------- K1: h1 = x @ W1 ; es1/ed1  (4 nodes x 16 feats / thread) --
__global__ __launch_bounds__(128)
void k_gemm1(const float* __restrict__ x, const float* __restrict__ W1,
             const float* __restrict__ a1s, const float* __restrict__ a1d) {
    __shared__ float Wsm[IN_DIM * H1F1];      // 32 KB, [k][64]
    __shared__ float Asm[64], Bsm[64];
    int tid = threadIdx.x;
    {
        const float4* w4 = (const float4*)W1;
        float4* s4 = (float4*)Wsm;
#pragma unroll
        for (int t = tid; t < IN_DIM * H1F1 / 4; t += 128) s4[t] = w4[t];
        if (tid < 64) { Asm[tid] = a1s[tid]; Bsm[tid] = a1d[tid]; }
    }
    __syncthreads();

    int fs   = tid >> 5;          // feature slice 0..3 -> feats [fs*16, fs*16+16)
    int lane = tid & 31;
    int base = blockIdx.x * 128;  // block covers 128 nodes

    int  n[4]; bool val[4];
    const float4* xr[4];
#pragma unroll
    for (int i = 0; i < 4; i++) {
        n[i]   = base + i * 32 + lane;
        val[i] = n[i] < N_NODES;
        int nr = val[i] ? n[i] : N_NODES - 1;
        xr[i]  = (const float4*)(x + (size_t)nr * IN_DIM);
    }

    float acc[4][16];
#pragma unroll
    for (int i = 0; i < 4; i++)
#pragma unroll
        for (int j = 0; j < 16; j++) acc[i][j] = 0.f;

#pragma unroll 2
    for (int kk = 0; kk < IN_DIM / 4; kk++) {
        float xs[4][4];
#pragma unroll
        for (int i = 0; i < 4; i++) {
            float4 xv = __ldg(xr[i] + kk);
            xs[i][0] = xv.x; xs[i][1] = xv.y; xs[i][2] = xv.z; xs[i][3] = xv.w;
        }
#pragma unroll
        for (int u = 0; u < 4; u++) {
            const float4* wr = (const float4*)&Wsm[(kk * 4 + u) * H1F1 + fs * 16];
            float4 w0 = wr[0], w1 = wr[1], w2 = wr[2], w3 = wr[3];
#pragma unroll
            for (int i = 0; i < 4; i++) {
                float xv = xs[i][u];
                acc[i][ 0] += xv * w0.x; acc[i][ 1] += xv * w0.y;
                acc[i][ 2] += xv * w0.z; acc[i][ 3] += xv * w0.w;
                acc[i][ 4] += xv * w1.x; acc[i][ 5] += xv * w1.y;
                acc[i][ 6] += xv * w1.z; acc[i][ 7] += xv * w1.w;
                acc[i][ 8] += xv * w2.x; acc[i][ 9] += xv * w2.y;
                acc[i][10] += xv * w2.z; acc[i][11] += xv * w2.w;
                acc[i][12] += xv * w3.x; acc[i][13] += xv * w3.y;
                acc[i][14] += xv * w3.z; acc[i][15] += xv * w3.w;
            }
        }
    }

    int h0 = fs * 2, h1 = fs * 2 + 1;   // the two heads this thread owns
#pragma unroll
    for (int i = 0; i < 4; i++) {
        if (!val[i]) continue;
        float4* ho = (float4*)&g_h1[(size_t)n[i] * H1F1 + fs * 16];
#pragma unroll
        for (int j4 = 0; j4 < 4; j4++)
            ho[j4] = make_float4(acc[i][j4*4+0], acc[i][j4*4+1],
                                 acc[i][j4*4+2], acc[i][j4*4+3]);
        float es0 = 0.f, ed0 = 0.f, es1 = 0.f, ed1 = 0.f;
#pragma unroll
        for (int f = 0; f < 8; f++) {
            es0 += acc[i][f]     * Asm[h0 * 8 + f];
            ed0 += acc[i][f]     * Bsm[h0 * 8 + f];
            es1 += acc[i][8 + f] * Asm[h1 * 8 + f];
            ed1 += acc[i][8 + f] * Bsm[h1 * 8 + f];
        }
        g_es1[n[i] * 8 + h0] = es0;  g_ed1[n[i] * 8 + h0] = ed0;
        g_es1[n[i] * 8 + h1] = es1;  g_ed1[n[i] * 8 + h1] = ed1;
    }
}

// ---------------- K2: layer1 CSR aggregate (1 warp per dst node) ------------
// simple per-edge loop (R6 form): idx load is warp-uniform and independent
// across iterations, so HW overlaps it with the dependent gathers.
__global__ __launch_bounds__(256)
void k_l1_csr() {
    int w    = (blockIdx.x * blockDim.x + threadIdx.x) >> 5;
    int lane = threadIdx.x & 31;
    if (w >= N_NODES) return;
    int d = w;
    float ed = __ldg(&g_ed1[d * 8 + (lane >> 2)]);   // lane's head = lane/4
    int beg = g_off[d], end = g_off[d + 1];
    float a0 = 0.f, a1 = 0.f, sw = 0.f;
    for (int j = beg; j < end; j++) {
        int s = g_eidx[j];                            // uniform across warp
        float es = __ldg(&g_es1[s * 8 + (lane >> 2)]);
        float wgt = pexp(es, ed);
        float2 h = *(const float2*)&g_h1[(size_t)s * H1F1 + lane * 2];
        a0 += wgt * h.x;
        a1 += wgt * h.y;
        sw += wgt;
    }
    float inv = 1.f / sw;
    *(float2*)&g_out1[(size_t)d * H1F1 + lane * 2] = make_float2(a0 * inv, a1 * inv);
}

// ---------------- K3: x2 = elu(out1) ; h2 = x2 @ W2 ; es2/ed2 ---------------
__global__ __launch_bounds__(256)
void k_gemm2(const float* __restrict__ W2,
             const float* __restrict__ a2s, const float* __restrict__ a2d) {
    __shared__ float Wsm[H1F1 * NCLS];   // 10 KB
    __shared__ float Asm[NCLS], Bsm[NCLS];
    int tid = threadIdx.x;
    for (int t = tid; t < H1F1 * NCLS; t += 256) Wsm[t] = W2[t];
    if (tid < NCLS) { Asm[tid] = a2s[tid]; Bsm[tid] = a2d[tid]; }
    __syncthreads();

    int node = blockIdx.x * 256 + tid;
    if (node >= N_NODES) return;

    float acc[NCLS];
#pragma unroll
    for (int c = 0; c < NCLS; c++) acc[c] = 0.f;

    const float4* xrow = (const float4*)&g_out1[(size_t)node * H1F1];
#pragma unroll 4
    for (int kk = 0; kk < H1F1 / 4; kk++) {
        float4 xv = xrow[kk];
        float xs4[4];
        xs4[0] = xv.x > 0.f ? xv.x : expm1f(xv.x);
        xs4[1] = xv.y > 0.f ? xv.y : expm1f(xv.y);
        xs4[2] = xv.z > 0.f ? xv.z : expm1f(xv.z);
        xs4[3] = xv.w > 0.f ? xv.w : expm1f(xv.w);
#pragma unroll
        for (int u = 0; u < 4; u++) {
            float xs = xs4[u];
            const float4* wr = (const float4*)&Wsm[(kk * 4 + u) * NCLS];
#pragma unroll
            for (int c4 = 0; c4 < NCLS / 4; c4++) {
                float4 w = wr[c4];
                acc[c4 * 4 + 0] += xs * w.x;
                acc[c4 * 4 + 1] += xs * w.y;
                acc[c4 * 4 + 2] += xs * w.z;
                acc[c4 * 4 + 3] += xs * w.w;
            }
        }
    }
    float4* hout = (float4*)&g_h2[(size_t)node * NCLS];
#pragma unroll
    for (int c4 = 0; c4 < NCLS / 4; c4++)
        hout[c4] = make_float4(acc[c4*4+0], acc[c4*4+1], acc[c4*4+2], acc[c4*4+3]);

    float es = 0.f, ed = 0.f;
#pragma unroll
    for (int c = 0; c < NCLS; c++) { es += acc[c] * Asm[c]; ed += acc[c] * Bsm[c]; }
    g_es2[node] = es;
    g_ed2[node] = ed;
}

// ---------------- K4: layer2 CSR aggregate + fused log_softmax --------------
__global__ __launch_bounds__(256)
void k_l2_csr(float* __restrict__ out) {
    int w    = (blockIdx.x * blockDim.x + threadIdx.x) >> 5;
    int lane = threadIdx.x & 31;
    if (w >= N_NODES) return;
    int d = w;
    float ed = __ldg(&g_ed2[d]);
    int beg = g_off[d], end = g_off[d + 1];
    float a0 = 0.f, a1 = 0.f, sw = 0.f;
    bool act = lane < NCLS / 2;
    for (int j = beg; j < end; j++) {
        int s = g_eidx[j];
        float es = __ldg(&g_es2[s]);
        float wgt = pexp(es, ed);
        if (act) {
            float2 h = *(const float2*)&g_h2[(size_t)s * NCLS + lane * 2];
            a0 += wgt * h.x;
            a1 += wgt * h.y;
        }
        sw += wgt;
    }
    float inv = 1.f / sw;
    float v0 = a0 * inv, v1 = a1 * inv;
    float m = act ? fmaxf(v0, v1) : -1e30f;
#pragma unroll
    for (int o = 16; o; o >>= 1) m = fmaxf(m, __shfl_xor_sync(0xffffffffu, m, o));
    float ssum = act ? (expf(v0 - m) + expf(v1 - m)) : 0.f;
#pragma unroll
    for (int o = 16; o; o >>= 1) ssum += __shfl_xor_sync(0xffffffffu, ssum, o);
    float lse = m + logf(ssum);
    if (act)
        *(float2*)&out[(size_t)d * NCLS + lane * 2] = make_float2(v0 - lse, v1 - lse);
}

// ---------------- launch ----------------------------------------------------
extern "C" void kernel_launch(void* const* d_in, const int* in_sizes, int n_in,
                              void* d_out, int out_size) {
    int ix = -1, ia = -1, iw1 = -1, iw2 = -1;
    int p64[2] = {-1, -1}, p40[2] = {-1, -1};
    for (int i = 0; i < n_in; i++) {
        switch (in_sizes[i]) {
            case N_NODES * IN_DIM:   ix  = i; break;
            case 2 * N_EDGES:        ia  = i; break;
            case IN_DIM * H1F1:      iw1 = i; break;
            case H1F1 * NCLS:        iw2 = i; break;
            case 64: (p64[0] < 0 ? p64[0] : p64[1]) = i; break;
            case 40: (p40[0] < 0 ? p40[0] : p40[1]) = i; break;
        }
    }
    bool alpha = (n_in > 0 && in_sizes[0] == IN_DIM * H1F1);
    int ia1s = alpha ? p64[1] : p64[0], ia1d = alpha ? p64[0] : p64[1];
    int ia2s = alpha ? p40[1] : p40[0], ia2d = alpha ? p40[0] : p40[1];

    const float* x   = (const float*)d_in[ix];
    const void*  adj = d_in[ia];
    const float* W1  = (const float*)d_in[iw1];
    const float* a1s = (const float*)d_in[ia1s];
    const float* a1d = (const float*)d_in[ia1d];
    const float* W2  = (const float*)d_in[iw2];
    const float* a2s = (const float*)d_in[ia2s];
    const float* a2d = (const float*)d_in[ia2d];
    float* out = (float*)d_out;

    const int TB = 256;
    int warpBlocks = (N_NODES * 32 + TB - 1) / TB;   // 1 warp per node

    k_detect<<<1, 32>>>((const long long*)adj);
    k_init_deg<<<(N_NODES + TB - 1) / TB, TB>>>();
    k_deg<<<(N_EDGES + TB - 1) / TB, TB>>>(adj);
    k_scan_local<<<SCAN_NB, SCAN_TB>>>();
    k_scan_base<<<1, 512>>>();
    k_scan_final<<<SCAN_NB, SCAN_TB>>>();
    k_scatter<<<(E_TOT + TB - 1) / TB, TB>>>(adj);
    k_gemm1<<<(N_NODES + 127) / 128, 128>>>(x, W1, a1s, a1d);
    k_l1_csr<<<warpBlocks, TB>>>();
    k_gemm2<<<(N_NODES + TB - 1) / TB, TB>>>(W2, a2s, a2d);
    k_l2_csr<<<warpBlocks, TB>>>(out);
}

// round 12
// speedup vs baseline: 1.1090x; 1.0574x over previous
#include <cuda_runtime.h>
#include <cuda_bf16.h>

#define N_NODES  100000
#define N_EDGES  3200000
#define E_TOT    (N_EDGES + N_NODES)   // edges + self loops
#define IN_DIM   128
#define H1F1     64                    // 8 heads x 8 feats
#define NCLS     40
#define NEG_SLOPE 0.2f
#define SCAN_TB  256
#define SCAN_NB  ((N_NODES + SCAN_TB - 1) / SCAN_TB)   // 391

// ---------------- scratch (static device globals; 16B-aligned) -------------
static __device__ __align__(16) int   g_deg [N_NODES];
static __device__ __align__(16) int   g_off [N_NODES + 1];
static __device__ __align__(16) int   g_cur [N_NODES];
static __device__ __align__(16) int   g_bsum [SCAN_NB];
static __device__ __align__(16) int   g_bbase[SCAN_NB];
static __device__ __align__(16) int   g_eidx[E_TOT];          // src per CSR slot
static __device__ __align__(16) float g_h1 [N_NODES * H1F1];
static __device__ __align__(16) float g_es1[N_NODES * 8];
static __device__ __align__(16) float g_ed1[N_NODES * 8];
static __device__ __align__(16) float g_out1[N_NODES * H1F1]; // normalized layer-1 output
static __device__ __align__(16) float g_h2 [N_NODES * NCLS];
static __device__ __align__(16) float g_es2[N_NODES];
static __device__ __align__(16) float g_ed2[N_NODES];
static __device__ int g_is64;

// exp(leaky_relu(a+b))
__device__ __forceinline__ float pexp(float a, float b) {
    float e = a + b;
    e = (e > 0.f) ? e : NEG_SLOPE * e;
    return __expf(e);
}

// ---------------- K_detect: adjacency int64 or int32? ----------------------
__global__ void k_detect(const long long* __restrict__ adj64) {
    if (blockIdx.x == 0 && threadIdx.x == 0) {
        int ok = 1;
        for (int i = 0; i < 64; i++) {
            long long v = adj64[i];
            if (v < 0 || v >= N_NODES) ok = 0;
        }
        g_is64 = ok;
    }
}

// ---------------- deg init: 1 (self loop) -----------------------------------
__global__ void k_init_deg() {
    int i = blockIdx.x * blockDim.x + threadIdx.x;
    if (i < N_NODES) g_deg[i] = 1;
}

// ---------------- degree histogram (reads dst half of adj only) -------------
__global__ void k_deg(const void* __restrict__ adjv) {
    int i = blockIdx.x * blockDim.x + threadIdx.x;
    if (i >= N_EDGES) return;
    int d;
    if (g_is64) d = (int)((const long long*)adjv)[i + N_EDGES];
    else        d = ((const int*)adjv)[i + N_EDGES];
    d = min(max(d, 0), N_NODES - 1);
    atomicAdd(&g_deg[d], 1);
}

// ---------------- 3-phase grid scan -----------------------------------------
__global__ __launch_bounds__(SCAN_TB)
void k_scan_local() {
    __shared__ int sh[SCAN_TB];
    int b = blockIdx.x, t = threadIdx.x;
    int i = b * SCAN_TB + t;
    int v = (i < N_NODES) ? g_deg[i] : 0;
    sh[t] = v;
    __syncthreads();
#pragma unroll
    for (int off = 1; off < SCAN_TB; off <<= 1) {
        int u = (t >= off) ? sh[t - off] : 0;
        __syncthreads();
        sh[t] += u;
        __syncthreads();
    }
    if (i < N_NODES) g_off[i] = sh[t] - v;
    if (t == SCAN_TB - 1) g_bsum[b] = sh[t];
}

__global__ __launch_bounds__(512)
void k_scan_base() {
    __shared__ int sh[512];
    int t = threadIdx.x;
    int v = (t < SCAN_NB) ? g_bsum[t] : 0;
    sh[t] = v;
    __syncthreads();
#pragma unroll
    for (int off = 1; off < 512; off <<= 1) {
        int u = (t >= off) ? sh[t - off] : 0;
        __syncthreads();
        sh[t] += u;
        __syncthreads();
    }
    if (t < SCAN_NB) g_bbase[t] = sh[t] - v;
}

__global__ __launch_bounds__(SCAN_TB)
void k_scan_final() {
    int b = blockIdx.x, t = threadIdx.x;
    int i = b * SCAN_TB + t;
    if (i < N_NODES) {
        int o = g_off[i] + g_bbase[b];
        g_off[i] = o;
        g_cur[i] = o;
    }
    if (i == 0) g_off[N_NODES] = E_TOT;
}

// ---------------- scatter: fill CSR src lists straight from adj -------------
__global__ void k_scatter(const void* __restrict__ adjv) {
    int e = blockIdx.x * blockDim.x + threadIdx.x;
    if (e >= E_TOT) return;
    int s, d;
    if (e < N_EDGES) {
        if (g_is64) {
            const long long* a = (const long long*)adjv;
            s = (int)a[e]; d = (int)a[e + N_EDGES];
        } else {
            const int* a = (const int*)adjv;
            s = a[e]; d = a[e + N_EDGES];
        }
        s = min(max(s, 0), N_NODES - 1);
        d = min(max(d, 0), N_NODES - 1);
    } else {
        s = d = e - N_EDGES;
    }
    int pos = atomicAdd(&g_cur[d], 1);
    g_eidx[pos] = s;
}

// ---------------- K1: h1 = x @ W1 ; es1/ed1  (4 nodes x 16 feats / thread) --
__global__ __launch_bounds__(128)
void k_gemm1(const float* __restrict__ x, const float* __restrict__ W1,
             const float* __restrict__ a1s, const float* __restrict__ a1d) {
    __shared__ float Wsm[IN_DIM * H1F1];      // 32 KB, [k][64]
    __shared__ float Asm[64], Bsm[64];
    int tid = threadIdx.x;
    {
        const float4* w4 = (const float4*)W1;
        float4* s4 = (float4*)Wsm;
#pragma unroll
        for (int t = tid; t < IN_DIM * H1F1 / 4; t += 128) s4[t] = w4[t];
        if (tid < 64) { Asm[tid] = a1s[tid]; Bsm[tid] = a1d[tid]; }
    }
    __syncthreads();

    int fs   = tid >> 5;          // feature slice 0..3 -> feats [fs*16, fs*16+16)
    int lane = tid & 31;
    int base = blockIdx.x * 128;  // block covers 128 nodes

    int  n[4]; bool val[4];
    const float4* xr[4];
#pragma unroll
    for (int i = 0; i < 4; i++) {
        n[i]   = base + i * 32 + lane;
        val[i] = n[i] < N_NODES;
        int nr = val[i] ? n[i] : N_NODES - 1;
        xr[i]  = (const float4*)(x + (size_t)nr * IN_DIM);
    }

    float acc[4][16];
#pragma unroll
    for (int i = 0; i < 4; i++)
#pragma unroll
        for (int j = 0; j < 16; j++) acc[i][j] = 0.f;

#pragma unroll 2
    for (int kk = 0; kk < IN_DIM / 4; kk++) {
        float xs[4][4];
#pragma unroll
        for (int i = 0; i < 4; i++) {
            float4 xv = __ldg(xr[i] + kk);
            xs[i][0] = xv.x; xs[i][1] = xv.y; xs[i][2] = xv.z; xs[i][3] = xv.w;
        }
#pragma unroll
        for (int u = 0; u < 4; u++) {
            const float4* wr = (const float4*)&Wsm[(kk * 4 + u) * H1F1 + fs * 16];
            float4 w0 = wr[0], w1 = wr[1], w2 = wr[2], w3 = wr[3];
#pragma unroll
            for (int i = 0; i < 4; i++) {
                float xv = xs[i][u];
                acc[i][ 0] += xv * w0.x; acc[i][ 1] += xv * w0.y;
                acc[i][ 2] += xv * w0.z; acc[i][ 3] += xv * w0.w;
                acc[i][ 4] += xv * w1.x; acc[i][ 5] += xv * w1.y;
                acc[i][ 6] += xv * w1.z; acc[i][ 7] += xv * w1.w;
                acc[i][ 8] += xv * w2.x; acc[i][ 9] += xv * w2.y;
                acc[i][10] += xv * w2.z; acc[i][11] += xv * w2.w;
                acc[i][12] += xv * w3.x; acc[i][13] += xv * w3.y;
                acc[i][14] += xv * w3.z; acc[i][15] += xv * w3.w;
            }
        }
    }

    int h0 = fs * 2, h1 = fs * 2 + 1;   // the two heads this thread owns
#pragma unroll
    for (int i = 0; i < 4; i++) {
        if (!val[i]) continue;
        float4* ho = (float4*)&g_h1[(size_t)n[i] * H1F1 + fs * 16];
#pragma unroll
        for (int j4 = 0; j4 < 4; j4++)
            ho[j4] = make_float4(acc[i][j4*4+0], acc[i][j4*4+1],
                                 acc[i][j4*4+2], acc[i][j4*4+3]);
        float es0 = 0.f, ed0 = 0.f, es1 = 0.f, ed1 = 0.f;
#pragma unroll
        for (int f = 0; f < 8; f++) {
            es0 += acc[i][f]     * Asm[h0 * 8 + f];
            ed0 += acc[i][f]     * Bsm[h0 * 8 + f];
            es1 += acc[i][8 + f] * Asm[h1 * 8 + f];
            ed1 += acc[i][8 + f] * Bsm[h1 * 8 + f];
        }
        g_es1[n[i] * 8 + h0] = es0;  g_ed1[n[i] * 8 + h0] = ed0;
        g_es1[n[i] * 8 + h1] = es1;  g_ed1[n[i] * 8 + h1] = ed1;
    }
}

// ---------------- K2: layer1 CSR aggregate (1 warp per dst node) ------------
__global__ __launch_bounds__(256)
void k_l1_csr() {
    int w    = (blockIdx.x * blockDim.x + threadIdx.x) >> 5;
    int lane = threadIdx.x & 31;
    if (w >= N_NODES) return;
    int d = w;
    float ed = __ldg(&g_ed1[d * 8 + (lane >> 2)]);   // lane's head = lane/4
    int beg = g_off[d], end = g_off[d + 1];
    float a0 = 0.f, a1 = 0.f, sw = 0.f;
    for (int j = beg; j < end; j++) {
        int s = g_eidx[j];                            // uniform across warp
        float es = __ldg(&g_es1[s * 8 + (lane >> 2)]);
        float wgt = pexp(es, ed);
        float2 h = *(const float2*)&g_h1[(size_t)s * H1F1 + lane * 2];
        a0 += wgt * h.x;
        a1 += wgt * h.y;
        sw += wgt;
    }
    float inv = 1.f / sw;
    *(float2*)&g_out1[(size_t)d * H1F1 + lane * 2] = make_float2(a0 * inv, a1 * inv);
}

// ---------------- K3: x2 = elu(out1) ; h2 = x2 @ W2 ; es2/ed2 ---------------
__global__ __launch_bounds__(256)
void k_gemm2(const float* __restrict__ W2,
             const float* __restrict__ a2s, const float* __restrict__ a2d) {
    __shared__ float Wsm[H1F1 * NCLS];   // 10 KB
    __shared__ float Asm[NCLS], Bsm[NCLS];
    int tid = threadIdx.x;
    for (int t = tid; t < H1F1 * NCLS; t += 256) Wsm[t] = W2[t];
    if (tid < NCLS) { Asm[tid] = a2s[tid]; Bsm[tid] = a2d[tid]; }
    __syncthreads();

    int node = blockIdx.x * 256 + tid;
    if (node >= N_NODES) return;

    float acc[NCLS];
#pragma unroll
    for (int c = 0; c < NCLS; c++) acc[c] = 0.f;

    const float4* xrow = (const float4*)&g_out1[(size_t)node * H1F1];
#pragma unroll 4
    for (int kk = 0; kk < H1F1 / 4; kk++) {
        float4 xv = xrow[kk];
        float xs4[4];
        xs4[0] = xv.x > 0.f ? xv.x : expm1f(xv.x);
        xs4[1] = xv.y > 0.f ? xv.y : expm1f(xv.y);
        xs4[2] = xv.z > 0.f ? xv.z : expm1f(xv.z);
        xs4[3] = xv.w > 0.f ? xv.w : expm1f(xv.w);
#pragma unroll
        for (int u = 0; u < 4; u++) {
            float xs = xs4[u];
            const float4* wr = (const float4*)&Wsm[(kk * 4 + u) * NCLS];
#pragma unroll
            for (int c4 = 0; c4 < NCLS / 4; c4++) {
                float4 w = wr[c4];
                acc[c4 * 4 + 0] += xs * w.x;
                acc[c4 * 4 + 1] += xs * w.y;
                acc[c4 * 4 + 2] += xs * w.z;
                acc[c4 * 4 + 3] += xs * w.w;
            }
        }
    }
    float4* hout = (float4*)&g_h2[(size_t)node * NCLS];
#pragma unroll
    for (int c4 = 0; c4 < NCLS / 4; c4++)
        hout[c4] = make_float4(acc[c4*4+0], acc[c4*4+1], acc[c4*4+2], acc[c4*4+3]);

    float es = 0.f, ed = 0.f;
#pragma unroll
    for (int c = 0; c < NCLS; c++) { es += acc[c] * Asm[c]; ed += acc[c] * Bsm[c]; }
    g_es2[node] = es;
    g_ed2[node] = ed;
}

// ---------------- K4: layer2 CSR aggregate + fused log_softmax --------------
__global__ __launch_bounds__(256)
void k_l2_csr(float* __restrict__ out) {
    int w    = (blockIdx.x * blockDim.x + threadIdx.x) >> 5;
    int lane = threadIdx.x & 31;
    if (w >= N_NODES) return;
    int d = w;
    float ed = __ldg(&g_ed2[d]);
    int beg = g_off[d], end = g_off[d + 1];
    float a0 = 0.f, a1 = 0.f, sw = 0.f;
    bool act = lane < NCLS / 2;
    for (int j = beg; j < end; j++) {
        int s = g_eidx[j];
        float es = __ldg(&g_es2[s]);
        float wgt = pexp(es, ed);
        if (act) {
            float2 h = *(const float2*)&g_h2[(size_t)s * NCLS + lane * 2];
            a0 += wgt * h.x;
            a1 += wgt * h.y;
        }
        sw += wgt;
    }
    float inv = 1.f / sw;
    float v0 = a0 * inv, v1 = a1 * inv;
    float m = act ? fmaxf(v0, v1) : -1e30f;
#pragma unroll
    for (int o = 16; o; o >>= 1) m = fmaxf(m, __shfl_xor_sync(0xffffffffu, m, o));
    float ssum = act ? (expf(v0 - m) + expf(v1 - m)) : 0.f;
#pragma unroll
    for (int o = 16; o; o >>= 1) ssum += __shfl_xor_sync(0xffffffffu, ssum, o);
    float lse = m + logf(ssum);
    if (act)
        *(float2*)&out[(size_t)d * NCLS + lane * 2] = make_float2(v0 - lse, v1 - lse);
}

// ---------------- launch ----------------------------------------------------
extern "C" void kernel_launch(void* const* d_in, const int* in_sizes, int n_in,
                              void* d_out, int out_size) {
    int ix = -1, ia = -1, iw1 = -1, iw2 = -1;
    int p64[2] = {-1, -1}, p40[2] = {-1, -1};
    for (int i = 0; i < n_in; i++) {
        switch (in_sizes[i]) {
            case N_NODES * IN_DIM:   ix  = i; break;
            case 2 * N_EDGES:        ia  = i; break;
            case IN_DIM * H1F1:      iw1 = i; break;
            case H1F1 * NCLS:        iw2 = i; break;
            case 64: (p64[0] < 0 ? p64[0] : p64[1]) = i; break;
            case 40: (p40[0] < 0 ? p40[0] : p40[1]) = i; break;
        }
    }
    bool alpha = (n_in > 0 && in_sizes[0] == IN_DIM * H1F1);
    int ia1s = alpha ? p64[1] : p64[0], ia1d = alpha ? p64[0] : p64[1];
    int ia2s = alpha ? p40[1] : p40[0], ia2d = alpha ? p40[0] : p40[1];

    const float* x   = (const float*)d_in[ix];
    const void*  adj = d_in[ia];
    const float* W1  = (const float*)d_in[iw1];
    const float* a1s = (const float*)d_in[ia1s];
    const float* a1d = (const float*)d_in[ia1d];
    const float* W2  = (const float*)d_in[iw2];
    const float* a2s = (const float*)d_in[ia2s];
    const float* a2d = (const float*)d_in[ia2d];
    float* out = (float*)d_out;

    const int TB = 256;
    int warpBlocks = (N_NODES * 32 + TB - 1) / TB;   // 1 warp per node

    // Fork-join: CSR build (uses only adj) runs parallel to k_gemm1 (uses x,W1).
    // Stream/event ops are capture-legal and host-side only (no device alloc).
    cudaStream_t s1;
    cudaStreamCreateWithFlags(&s1, cudaStreamNonBlocking);
    cudaEvent_t eFork, eJoin;
    cudaEventCreateWithFlags(&eFork, cudaEventDisableTiming);
    cudaEventCreateWithFlags(&eJoin, cudaEventDisableTiming);

    cudaEventRecord(eFork, 0);
    cudaStreamWaitEvent(s1, eFork, 0);

    // --- CSR branch (stream s1) ---
    k_detect<<<1, 32, 0, s1>>>((const long long*)adj);
    k_init_deg<<<(N_NODES + TB - 1) / TB, TB, 0, s1>>>();
    k_deg<<<(N_EDGES + TB - 1) / TB, TB, 0, s1>>>(adj);
    k_scan_local<<<SCAN_NB, SCAN_TB, 0, s1>>>();
    k_scan_base<<<1, 512, 0, s1>>>();
    k_scan_final<<<SCAN_NB, SCAN_TB, 0, s1>>>();
    k_scatter<<<(E_TOT + TB - 1) / TB, TB, 0, s1>>>(adj);
    cudaEventRecord(eJoin, s1);

    // --- dense branch (default stream), concurrent with CSR build ---
    k_gemm1<<<(N_NODES + 127) / 128, 128>>>(x, W1, a1s, a1d);

    // --- join, then the serial tail ---
    cudaStreamWaitEvent(0, eJoin, 0);
    k_l1_csr<<<warpBlocks, TB>>>();
    k_gemm2<<<(N_NODES + TB - 1) / TB, TB>>>(W2, a2s, a2d);
    k_l2_csr<<<warpBlocks, TB>>>(out);

    cudaEventDestroy(eFork);
    cudaEventDestroy(eJoin);
    cudaStreamDestroy(s1);
}